// round 16
// baseline (speedup 1.0000x reference)
#include <cuda_runtime.h>
#include <cstdint>

// TwistJMotorInt8: 4 rounds of {row-max quantize to +-42 ints, integer MJ
// butterfly on groups of 4 (rolled by 2 on Thue-Morse odd steps), dequantize},
// then out = x*scale + bias.  One CTA per 4096-float row.
//
// Verified bit-exact numerics (rel_err == 0.0 since R14) — DO NOT CHANGE:
//   qs = RN(max * RN(1/42));  r = div.rn(1, qs)
//   q  = clip(roundeven(RN(x * r)), -42, 42)
//   dequant = RN(y * qs); epilogue = separate RN mul / RN add.
//
// R16 perf change: 512 threads x 8 elems/thread (was 256 x 16) to cut
// register pressure (~48 -> ~34 regs) and double occupancy; per-step
// dependency chains halve.  Same 1-barrier/step, halo-pair roll scheme.

#define DIM     4096
#define THREADS 512            // == DIM/8; ring of threads spans one row

__device__ __forceinline__ float clipq(float x, float r) {
    float d = rintf(__fmul_rn(x, r));
    return fminf(fmaxf(d, -42.0f), 42.0f);
}

__global__ void __launch_bounds__(THREADS)
twist_kernel(const float* __restrict__ x,
             const float* __restrict__ scale,
             const float* __restrict__ bias,
             float* __restrict__ out)
{
    __shared__ __align__(16) unsigned s_red[2][16];  // per-parity max partials
    __shared__ float2 sA[2][THREADS];                // (v[0], v[1]) per roll step
    __shared__ float2 sB[2][THREADS];                // (v[6], v[7]) per roll step

    const int t    = threadIdx.x;
    const int lane = t & 31;
    const int wid  = t >> 5;
    const long long rowbase = (long long)blockIdx.x * DIM;

    // Coalesced load: elements 8t .. 8t+7 (two float4 per thread).
    float v[8];
    const float4* __restrict__ xin = (const float4*)(x + rowbase) + t * 2;
    {
        float4 w0 = xin[0], w1 = xin[1];
        v[0] = w0.x; v[1] = w0.y; v[2] = w0.z; v[3] = w0.w;
        v[4] = w1.x; v[5] = w1.y; v[6] = w1.z; v[7] = w1.w;
    }

    const float inv42 = 1.0f / 42.0f;   // RN(1/42)

    #pragma unroll
    for (int step = 0; step < 4; step++) {
        const int  p    = step & 1;
        const bool roll = (step == 1) || (step == 2);   // Thue-Morse 0,1,1,0
        const int  rb   = step - 1;                     // halo buffer (1->0, 2->1)

        // ---- warp-level max of |v| (bit-monotonic for non-negative f32) ----
        float m = fabsf(v[0]);
        #pragma unroll
        for (int i = 1; i < 8; i++) m = fmaxf(m, fabsf(v[i]));
        unsigned um = __reduce_max_sync(0xffffffffu, __float_as_uint(m));
        if (lane == 0) s_red[p][wid] = um;

        // ---- stage 2-element halo pairs (roll steps only) ----
        if (roll) {
            sA[rb][t] = make_float2(v[0], v[1]);
            sB[rb][t] = make_float2(v[6], v[7]);
        }
        __syncthreads();   // serves both the reduction and the halo exchange

        // ---- finish max across 16 warps (four uint4 broadcasts) ----
        const uint4* sr = (const uint4*)s_red[p];
        uint4 a = sr[0], b = sr[1], c = sr[2], d = sr[3];
        unsigned mm = max(max(max(max(a.x, a.y), max(a.z, a.w)),
                              max(max(b.x, b.y), max(b.z, b.w))),
                          max(max(max(c.x, c.y), max(c.z, c.w)),
                              max(max(d.x, d.y), max(d.z, d.w))));
        const float maxv = fmaxf(__uint_as_float(mm), 1e-12f);
        const float qs   = __fmul_rn(maxv, inv42);   // dequant scale
        const float r    = __fdiv_rn(1.0f, qs);      // hoisted RN reciprocal

        if (roll) {
            // Neighbor halo (ring of 512 threads == one 4096 row).
            const float2 L = sB[rb][(t + THREADS - 1) & (THREADS - 1)];
            const float2 R = sA[rb][(t + 1) & (THREADS - 1)];

            // Extended quantized window qe[0..11] = q[8t-2 .. 8t+9].
            float qe[12];
            qe[0] = clipq(L.x, r);  qe[1] = clipq(L.y, r);
            #pragma unroll
            for (int i = 0; i < 8; i++) qe[2 + i] = clipq(v[i], r);
            qe[10] = clipq(R.x, r); qe[11] = clipq(R.y, r);

            // Composite roll(+2) -> MJ -> roll(-2) per 4-group:
            //   y[g+0] = q[g-2]
            //   y[g+1] = q[g-1] - q[g]   + q[g+1]
            //   y[g+2] = q[g+2] - q[g+4] + q[g+5]
            //   y[g+3] = q[g+3] - q[g+4]
            #pragma unroll
            for (int k = 0; k < 2; k++) {
                const int g = 2 + 4 * k;     // qe index of group base
                v[4*k+0] = qe[g-2];
                v[4*k+1] = qe[g-1] - qe[g]   + qe[g+1];
                v[4*k+2] = qe[g+2] - qe[g+4] + qe[g+5];
                v[4*k+3] = qe[g+3] - qe[g+4];
            }
        } else {
            // MJ in registers: y = [x0-x2+x3, x1-x2, x0, x1-x2+x3]
            #pragma unroll
            for (int k = 0; k < 2; k++) {
                const float x0 = clipq(v[4*k+0], r);
                const float x1 = clipq(v[4*k+1], r);
                const float x2 = clipq(v[4*k+2], r);
                const float x3 = clipq(v[4*k+3], r);
                const float y1 = x1 - x2;
                v[4*k+0] = x0 - x2 + x3;
                v[4*k+1] = y1;
                v[4*k+2] = x0;
                v[4*k+3] = y1 + x3;
            }
        }

        // ---- dequantize (exact RN multiply, small-integer * qs) ----
        #pragma unroll
        for (int i = 0; i < 8; i++) v[i] = __fmul_rn(v[i], qs);
    }

    // ---- epilogue: out = v*scale + bias (separate RN mul, RN add) ----
    float4* __restrict__ o4 = (float4*)(out + rowbase) + t * 2;
    const float4* __restrict__ sc4 = (const float4*)scale + t * 2;
    const float4* __restrict__ bi4 = (const float4*)bias  + t * 2;
    #pragma unroll
    for (int c2 = 0; c2 < 2; c2++) {
        const float4 s = __ldg(sc4 + c2);
        const float4 b = __ldg(bi4 + c2);
        float4 rr;
        rr.x = __fadd_rn(__fmul_rn(v[4*c2+0], s.x), b.x);
        rr.y = __fadd_rn(__fmul_rn(v[4*c2+1], s.y), b.y);
        rr.z = __fadd_rn(__fmul_rn(v[4*c2+2], s.z), b.z);
        rr.w = __fadd_rn(__fmul_rn(v[4*c2+3], s.w), b.w);
        o4[c2] = rr;
    }
}

extern "C" void kernel_launch(void* const* d_in, const int* in_sizes, int n_in,
                              void* d_out, int out_size) {
    const float* x     = (const float*)d_in[0];
    const float* scale = (const float*)d_in[1];
    const float* bias  = (const float*)d_in[2];
    float* out         = (float*)d_out;
    const int rows = in_sizes[0] / DIM;   // 16384
    twist_kernel<<<rows, THREADS>>>(x, scale, bias, out);
}

// round 17
// speedup vs baseline: 1.5593x; 1.5593x over previous
#include <cuda_runtime.h>
#include <cstdint>

// TwistJMotorInt8: 4 rounds of {row-max quantize to +-42 ints, integer MJ
// butterfly on groups of 4 (rolled by 2 on Thue-Morse odd steps), dequantize},
// then out = x*scale + bias.
//
// Verified bit-exact numerics (rel_err == 0.0 since R14) — DO NOT CHANGE:
//   qs = RN(max * RN(1/42));  r = div.rn(1, qs)
//   q  = clip(roundeven(RN(x * r)), -42, 42)
//   dequant = RN(y * qs); epilogue = separate RN mul / RN add.
//
// R17 perf change vs R15: each CTA processes 8 rows sequentially with
// scale/bias held in registers (loaded once) — cuts the redundant per-CTA
// scale/bias L1 traffic 8x (it was half of all L1 bytes, the binding pipe).
// Thread layout stays 256 x 16 (R16 showed 512 x 8 is ALU-overhead-bound).

#define DIM     4096
#define THREADS 256
#define ROWS    8              // rows per CTA

__device__ __forceinline__ float clipq(float x, float r) {
    float d = rintf(__fmul_rn(x, r));
    return fminf(fmaxf(d, -42.0f), 42.0f);
}

__global__ void __launch_bounds__(THREADS)
twist_kernel(const float* __restrict__ x,
             const float* __restrict__ scale,
             const float* __restrict__ bias,
             float* __restrict__ out)
{
    __shared__ __align__(16) unsigned s_red[2][8];  // per-parity max partials
    __shared__ float2 sA[2][THREADS];               // (v[0], v[1])  per roll step
    __shared__ float2 sB[2][THREADS];               // (v[14],v[15]) per roll step

    const int t    = threadIdx.x;
    const int lane = t & 31;
    const int wid  = t >> 5;

    const float inv42 = 1.0f / 42.0f;   // RN(1/42)

    // ---- load scale/bias ONCE per CTA (columns 16t .. 16t+15) ----
    float4 sc[4], bi[4];
    {
        const float4* __restrict__ sc4 = (const float4*)scale + t * 4;
        const float4* __restrict__ bi4 = (const float4*)bias  + t * 4;
        #pragma unroll
        for (int c = 0; c < 4; c++) { sc[c] = __ldg(sc4 + c); bi[c] = __ldg(bi4 + c); }
    }

    #pragma unroll 1
    for (int row = 0; row < ROWS; row++) {
        const long long rowbase =
            ((long long)blockIdx.x * ROWS + row) * DIM;

        // Coalesced load: elements 16t .. 16t+15.
        float v[16];
        const float4* __restrict__ xin = (const float4*)(x + rowbase) + t * 4;
        #pragma unroll
        for (int c = 0; c < 4; c++) {
            float4 w = xin[c];
            v[4*c+0] = w.x; v[4*c+1] = w.y; v[4*c+2] = w.z; v[4*c+3] = w.w;
        }

        #pragma unroll
        for (int step = 0; step < 4; step++) {
            const int  p    = step & 1;
            const bool roll = (step == 1) || (step == 2); // Thue-Morse 0,1,1,0
            const int  rb   = step - 1;                   // halo buffer (1->0, 2->1)

            // ---- warp max of |v| (bit-monotonic for non-negative f32) ----
            float m = fabsf(v[0]);
            #pragma unroll
            for (int i = 1; i < 16; i++) m = fmaxf(m, fabsf(v[i]));
            unsigned um = __reduce_max_sync(0xffffffffu, __float_as_uint(m));
            if (lane == 0) s_red[p][wid] = um;

            // ---- stage 2-element halo pairs (roll steps only) ----
            if (roll) {
                sA[rb][t] = make_float2(v[0],  v[1]);
                sB[rb][t] = make_float2(v[14], v[15]);
            }
            __syncthreads();   // reduction + halo exchange share this barrier
            // (Cross-row WAR on s_red/sA/sB is safe: every buffer's next
            //  write is separated from its previous readers by >=1 barrier.)

            // ---- finish max across 8 warps (two uint4 broadcasts) ----
            const uint4* sr = (const uint4*)s_red[p];
            uint4 a = sr[0], b = sr[1];
            unsigned mm = max(max(max(a.x, a.y), max(a.z, a.w)),
                              max(max(b.x, b.y), max(b.z, b.w)));
            const float maxv = fmaxf(__uint_as_float(mm), 1e-12f);
            const float qs   = __fmul_rn(maxv, inv42);   // dequant scale
            const float r    = __fdiv_rn(1.0f, qs);      // hoisted reciprocal

            if (roll) {
                const float2 L = sB[rb][(t + THREADS - 1) & (THREADS - 1)];
                const float2 R = sA[rb][(t + 1) & (THREADS - 1)];

                // Extended quantized window qe[0..19] = q[16t-2 .. 16t+17].
                float qe[20];
                qe[0] = clipq(L.x, r);  qe[1] = clipq(L.y, r);
                #pragma unroll
                for (int i = 0; i < 16; i++) qe[2 + i] = clipq(v[i], r);
                qe[18] = clipq(R.x, r); qe[19] = clipq(R.y, r);

                // roll(+2) -> MJ -> roll(-2) composite per 4-group.
                #pragma unroll
                for (int k = 0; k < 4; k++) {
                    const int g = 2 + 4 * k;
                    v[4*k+0] = qe[g-2];
                    v[4*k+1] = qe[g-1] - qe[g]   + qe[g+1];
                    v[4*k+2] = qe[g+2] - qe[g+4] + qe[g+5];
                    v[4*k+3] = qe[g+3] - qe[g+4];
                }
            } else {
                // MJ in registers: y = [x0-x2+x3, x1-x2, x0, x1-x2+x3]
                #pragma unroll
                for (int k = 0; k < 4; k++) {
                    const float x0 = clipq(v[4*k+0], r);
                    const float x1 = clipq(v[4*k+1], r);
                    const float x2 = clipq(v[4*k+2], r);
                    const float x3 = clipq(v[4*k+3], r);
                    const float y1 = x1 - x2;
                    v[4*k+0] = x0 - x2 + x3;
                    v[4*k+1] = y1;
                    v[4*k+2] = x0;
                    v[4*k+3] = y1 + x3;
                }
            }

            // ---- dequantize (exact RN multiply, small-integer * qs) ----
            #pragma unroll
            for (int i = 0; i < 16; i++) v[i] = __fmul_rn(v[i], qs);
        }

        // ---- epilogue: out = v*scale + bias (separate RN mul, RN add) ----
        float4* __restrict__ o4 = (float4*)(out + rowbase) + t * 4;
        #pragma unroll
        for (int c = 0; c < 4; c++) {
            float4 rr;
            rr.x = __fadd_rn(__fmul_rn(v[4*c+0], sc[c].x), bi[c].x);
            rr.y = __fadd_rn(__fmul_rn(v[4*c+1], sc[c].y), bi[c].y);
            rr.z = __fadd_rn(__fmul_rn(v[4*c+2], sc[c].z), bi[c].z);
            rr.w = __fadd_rn(__fmul_rn(v[4*c+3], sc[c].w), bi[c].w);
            o4[c] = rr;
        }
    }
}

extern "C" void kernel_launch(void* const* d_in, const int* in_sizes, int n_in,
                              void* d_out, int out_size) {
    const float* x     = (const float*)d_in[0];
    const float* scale = (const float*)d_in[1];
    const float* bias  = (const float*)d_in[2];
    float* out         = (float*)d_out;
    const int rows = in_sizes[0] / DIM;        // 16384
    const int grid = rows / ROWS;              // 2048
    twist_kernel<<<grid, THREADS>>>(x, scale, bias, out);
}